// round 3
// baseline (speedup 1.0000x reference)
#include <cuda_runtime.h>
#include <math_constants.h>
#include <mma.h>
#include <cstdint>

using namespace nvcuda;

// ---------------------------------------------------------------------------
// Problem constants
// ---------------------------------------------------------------------------
#define B_  2
#define S_  2048
#define D_  768
#define F_  3072
#define H_  12
#define HD_ 64
#define M_  (B_ * S_)   // 4096 rows

// ---------------------------------------------------------------------------
// Scratch
// ---------------------------------------------------------------------------
__device__ float g_Q[M_ * D_];
__device__ float g_K[M_ * D_];
__device__ float g_V[M_ * D_];
__device__ float g_attn[M_ * D_];
__device__ float g_t1[M_ * D_];
__device__ float g_x1[M_ * D_];
__device__ float g_ff[(size_t)M_ * F_];
__device__ float g_t2[M_ * D_];

// ---------------------------------------------------------------------------
// TF32 helpers — NOTE: cvt.rna.tf32.f32 requires a b32 destination register.
// ---------------------------------------------------------------------------
__device__ __forceinline__ float tf32_rna(float x) {
    uint32_t r;
    asm("cvt.rna.tf32.f32 %0, %1;" : "=r"(r) : "f"(x));
    return __uint_as_float(r);
}

using FragA  = wmma::fragment<wmma::matrix_a, 16, 16, 8, wmma::precision::tf32, wmma::row_major>;
using FragBr = wmma::fragment<wmma::matrix_b, 16, 16, 8, wmma::precision::tf32, wmma::row_major>;
using FragBc = wmma::fragment<wmma::matrix_b, 16, 16, 8, wmma::precision::tf32, wmma::col_major>;
using FragC  = wmma::fragment<wmma::accumulator, 16, 16, 8, float>;

// ---------------------------------------------------------------------------
// 3xTF32 GEMM: C[M,N] = A[M,K] @ W[K,N] + bias (+resid) (+ReLU)
// CTA tile 128x128, BK=32, 256 threads = 8 warps (2x4), warp tile 64x32.
// ---------------------------------------------------------------------------
template <bool RELU, bool RES>
__device__ __forceinline__ void gemm_body(
    const float* __restrict__ A, const float* __restrict__ W,
    const float* __restrict__ bias, const float* __restrict__ resid,
    float* __restrict__ C, int N, int K, int bm, int bn)
{
    __shared__ float As[128][40];
    __shared__ float Bs[32][136];
    __shared__ float bias_s[16][136];

    const int tid = threadIdx.x;
    const int wid = tid >> 5;
    const int wm = wid & 1;   // 0..1  (M)
    const int wn = wid >> 1;  // 0..3  (N)

    // replicate bias across 16 rows (for accumulator-layout fragment loads)
    #pragma unroll
    for (int p = 0; p < 8; p++) {
        int idx = tid + p * 256;
        bias_s[idx >> 7][idx & 127] = bias[bn + (idx & 127)];
    }

    FragC acc[4][2];
    #pragma unroll
    for (int i = 0; i < 4; i++)
        #pragma unroll
        for (int j = 0; j < 2; j++)
            wmma::fill_fragment(acc[i][j], 0.0f);

    const int arow = tid >> 3, acol = (tid & 7) << 2;
    const int brow = tid >> 5, bcol = (tid & 31) << 2;

    for (int kt = 0; kt < K; kt += 32) {
        #pragma unroll
        for (int p = 0; p < 4; p++) {
            *(float4*)&As[arow + p * 32][acol] =
                *(const float4*)&A[(size_t)(bm + arow + p * 32) * K + kt + acol];
            *(float4*)&Bs[brow + p * 8][bcol] =
                *(const float4*)&W[(size_t)(kt + brow + p * 8) * N + bn + bcol];
        }
        __syncthreads();

        #pragma unroll
        for (int kk = 0; kk < 32; kk += 8) {
            FragA ahi[4], alo[4];
            #pragma unroll
            for (int i = 0; i < 4; i++) {
                FragA a;
                wmma::load_matrix_sync(a, &As[wm * 64 + i * 16][kk], 40);
                #pragma unroll
                for (int t = 0; t < a.num_elements; t++) {
                    float v = a.x[t];
                    float h = tf32_rna(v);
                    ahi[i].x[t] = h;
                    alo[i].x[t] = tf32_rna(v - h);
                }
            }
            #pragma unroll
            for (int j = 0; j < 2; j++) {
                FragBr b, bhi, blo;
                wmma::load_matrix_sync(b, &Bs[kk][wn * 32 + j * 16], 136);
                #pragma unroll
                for (int t = 0; t < b.num_elements; t++) {
                    float v = b.x[t];
                    float h = tf32_rna(v);
                    bhi.x[t] = h;
                    blo.x[t] = tf32_rna(v - h);
                }
                #pragma unroll
                for (int i = 0; i < 4; i++) {
                    wmma::mma_sync(acc[i][j], ahi[i], bhi, acc[i][j]);
                    wmma::mma_sync(acc[i][j], ahi[i], blo, acc[i][j]);
                    wmma::mma_sync(acc[i][j], alo[i], bhi, acc[i][j]);
                }
            }
        }
        __syncthreads();
    }

    // epilogue: bias (+resid) (+relu), store straight to global
    #pragma unroll
    for (int i = 0; i < 4; i++) {
        int r0 = bm + wm * 64 + i * 16;
        #pragma unroll
        for (int j = 0; j < 2; j++) {
            int c0 = bn + wn * 32 + j * 16;
            FragC bf;
            wmma::load_matrix_sync(bf, &bias_s[0][wn * 32 + j * 16], 136, wmma::mem_row_major);
            #pragma unroll
            for (int t = 0; t < acc[i][j].num_elements; t++)
                acc[i][j].x[t] += bf.x[t];
            if (RES) {
                FragC rf;
                wmma::load_matrix_sync(rf, resid + (size_t)r0 * N + c0, N, wmma::mem_row_major);
                #pragma unroll
                for (int t = 0; t < acc[i][j].num_elements; t++)
                    acc[i][j].x[t] += rf.x[t];
            }
            if (RELU) {
                #pragma unroll
                for (int t = 0; t < acc[i][j].num_elements; t++)
                    acc[i][j].x[t] = fmaxf(acc[i][j].x[t], 0.0f);
            }
            wmma::store_matrix_sync(C + (size_t)r0 * N + c0, acc[i][j], N, wmma::mem_row_major);
        }
    }
}

template <bool RELU, bool RES>
__global__ __launch_bounds__(256)
void gemm_tc(const float* __restrict__ A, const float* __restrict__ W,
             const float* __restrict__ bias, const float* __restrict__ resid,
             float* __restrict__ C, int N, int K)
{
    gemm_body<RELU, RES>(A, W, bias, resid, C, N, K,
                         blockIdx.y * 128, blockIdx.x * 128);
}

// Fused QKV: blockIdx.z selects projection
__global__ __launch_bounds__(256)
void qkv_tc(const float* __restrict__ x,
            const float* __restrict__ Wq, const float* __restrict__ bq,
            const float* __restrict__ Wk, const float* __restrict__ bk,
            const float* __restrict__ Wv, const float* __restrict__ bv,
            float* __restrict__ Q, float* __restrict__ K, float* __restrict__ V)
{
    const float* W = blockIdx.z == 0 ? Wq : (blockIdx.z == 1 ? Wk : Wv);
    const float* bb = blockIdx.z == 0 ? bq : (blockIdx.z == 1 ? bk : bv);
    float* C = blockIdx.z == 0 ? Q : (blockIdx.z == 1 ? K : V);
    gemm_body<false, false>(x, W, bb, nullptr, C, D_, D_,
                            blockIdx.y * 128, blockIdx.x * 128);
}

// ---------------------------------------------------------------------------
// Flash-ish attention with wmma. 64 q-rows per CTA, key blocks of 64.
// No running max (scores bounded; clamp at 80 as inf-guard) -> O accumulates
// in fragments with no row rescale; single 1/l normalize at the end.
// QK^T uses 3xTF32 (exp amplifies absolute score error); PV uses 1xTF32.
// Dyn smem: Qs[64][68] + Ks[64][68] + Ss[64][68] + l[64] = 52480 B.
// ---------------------------------------------------------------------------
__global__ __launch_bounds__(256)
void attn_tc(const float* __restrict__ Q, const float* __restrict__ K,
             const float* __restrict__ V, float* __restrict__ O)
{
    extern __shared__ float sm[];
    float* Qs = sm;                 // [64][68]
    float* Ks = sm + 64 * 68;       // [64][68]  (K tile, then V tile)
    float* Ss = sm + 2 * 64 * 68;   // [64][68]  (scores / P / final O staging)
    float* lrow = sm + 3 * 64 * 68; // [64]

    const int tid = threadIdx.x;
    const int wid = tid >> 5;
    const int wm = wid & 1;    // 0..1 -> 32-row half
    const int wn = wid >> 1;   // 0..3 -> 16-col slice
    const int bh = blockIdx.y;
    const int b = bh / H_;
    const int h = bh % H_;
    const int q0 = blockIdx.x * 64;
    const size_t hb = (size_t)b * S_ * D_ + (size_t)h * HD_;

    const int lr = tid >> 2;          // 0..63 row
    const int lc = (tid & 3) << 4;    // 0,16,32,48

    // Q tile (scale 1/sqrt(64) folded in)
    {
        const float* src = Q + hb + (size_t)(q0 + lr) * D_ + lc;
        #pragma unroll
        for (int i = 0; i < 4; i++) {
            float4 v = *(const float4*)(src + i * 4);
            v.x *= 0.125f; v.y *= 0.125f; v.z *= 0.125f; v.w *= 0.125f;
            *(float4*)&Qs[lr * 68 + lc + i * 4] = v;
        }
    }
    if (tid < 64) lrow[tid] = 0.0f;

    FragC oacc[2];
    wmma::fill_fragment(oacc[0], 0.0f);
    wmma::fill_fragment(oacc[1], 0.0f);

    for (int kt = 0; kt < S_; kt += 64) {
        // K tile (natural [key][d]; serves as col-major B for Q.K^T)
        {
            const float* src = K + hb + (size_t)(kt + lr) * D_ + lc;
            #pragma unroll
            for (int i = 0; i < 4; i++)
                *(float4*)&Ks[lr * 68 + lc + i * 4] = *(const float4*)(src + i * 4);
        }
        __syncthreads();

        // S = Q @ K^T  (3xTF32)
        FragC sacc[2];
        wmma::fill_fragment(sacc[0], 0.0f);
        wmma::fill_fragment(sacc[1], 0.0f);
        #pragma unroll
        for (int dd = 0; dd < 64; dd += 8) {
            FragA ahi[2], alo[2];
            #pragma unroll
            for (int i = 0; i < 2; i++) {
                FragA a;
                wmma::load_matrix_sync(a, &Qs[(wm * 32 + i * 16) * 68 + dd], 68);
                #pragma unroll
                for (int t = 0; t < a.num_elements; t++) {
                    float v = a.x[t];
                    float hh = tf32_rna(v);
                    ahi[i].x[t] = hh;
                    alo[i].x[t] = tf32_rna(v - hh);
                }
            }
            FragBc bb, bhi, blo;
            wmma::load_matrix_sync(bb, &Ks[(wn * 16) * 68 + dd], 68);
            #pragma unroll
            for (int t = 0; t < bb.num_elements; t++) {
                float v = bb.x[t];
                float hh = tf32_rna(v);
                bhi.x[t] = hh;
                blo.x[t] = tf32_rna(v - hh);
            }
            #pragma unroll
            for (int i = 0; i < 2; i++) {
                wmma::mma_sync(sacc[i], ahi[i], bhi, sacc[i]);
                wmma::mma_sync(sacc[i], ahi[i], blo, sacc[i]);
                wmma::mma_sync(sacc[i], alo[i], bhi, sacc[i]);
            }
        }
        #pragma unroll
        for (int i = 0; i < 2; i++)
            wmma::store_matrix_sync(&Ss[(wm * 32 + i * 16) * 68 + wn * 16],
                                    sacc[i], 68, wmma::mem_row_major);
        __syncthreads();

        // exp (no max-shift) + row-sum accumulation, and stage V into Ks
        {
            int row = tid >> 2;
            float* p = &Ss[row * 68 + ((tid & 3) << 4)];
            float s = 0.0f;
            #pragma unroll
            for (int i = 0; i < 16; i++) {
                float e = __expf(fminf(p[i], 80.0f));
                p[i] = e;
                s += e;
            }
            s += __shfl_xor_sync(0xffffffffu, s, 1);
            s += __shfl_xor_sync(0xffffffffu, s, 2);
            if ((tid & 3) == 0) lrow[row] += s;

            const float* src = V + hb + (size_t)(kt + lr) * D_ + lc;
            #pragma unroll
            for (int i = 0; i < 4; i++)
                *(float4*)&Ks[lr * 68 + lc + i * 4] = *(const float4*)(src + i * 4);
        }
        __syncthreads();

        // O += P @ V  (1xTF32)
        #pragma unroll
        for (int kk = 0; kk < 64; kk += 8) {
            FragA a[2];
            #pragma unroll
            for (int i = 0; i < 2; i++) {
                wmma::load_matrix_sync(a[i], &Ss[(wm * 32 + i * 16) * 68 + kk], 68);
                #pragma unroll
                for (int t = 0; t < a[i].num_elements; t++)
                    a[i].x[t] = tf32_rna(a[i].x[t]);
            }
            FragBr bb;
            wmma::load_matrix_sync(bb, &Ks[kk * 68 + wn * 16], 68);
            #pragma unroll
            for (int t = 0; t < bb.num_elements; t++)
                bb.x[t] = tf32_rna(bb.x[t]);
            #pragma unroll
            for (int i = 0; i < 2; i++)
                wmma::mma_sync(oacc[i], a[i], bb, oacc[i]);
        }
        __syncthreads();  // before next block overwrites Ks/Ss
    }

    // normalize by 1/l and write out
    #pragma unroll
    for (int i = 0; i < 2; i++)
        wmma::store_matrix_sync(&Ss[(wm * 32 + i * 16) * 68 + wn * 16],
                                oacc[i], 68, wmma::mem_row_major);
    __syncthreads();
    {
        int row = tid >> 2;
        float inv = 1.0f / lrow[row];
        float* p = &Ss[row * 68 + lc];
        float* dst = O + (size_t)((size_t)b * S_ + q0 + row) * D_ + h * HD_ + lc;
        #pragma unroll
        for (int i = 0; i < 4; i++) {
            float4 v = *(float4*)&p[i * 4];
            v.x *= inv; v.y *= inv; v.z *= inv; v.w *= inv;
            *(float4*)(dst + i * 4) = v;
        }
    }
}

// ---------------------------------------------------------------------------
// Row LayerNorm over D_=768 columns. One CTA per row.
// ---------------------------------------------------------------------------
__global__ __launch_bounds__(256)
void ln_kernel(const float* __restrict__ X, const float* __restrict__ g,
               const float* __restrict__ be, float* __restrict__ Y)
{
    const int row = blockIdx.x;
    const float* xr = X + (size_t)row * D_;
    float v[3];
    float s = 0.f, ss = 0.f;
    #pragma unroll
    for (int i = 0; i < 3; i++) {
        v[i] = xr[threadIdx.x + i * 256];
        s += v[i];
        ss += v[i] * v[i];
    }
    #pragma unroll
    for (int o = 16; o; o >>= 1) {
        s += __shfl_xor_sync(0xffffffffu, s, o);
        ss += __shfl_xor_sync(0xffffffffu, ss, o);
    }
    __shared__ float red[16];
    const int wid = threadIdx.x >> 5, lid = threadIdx.x & 31;
    if (lid == 0) { red[wid] = s; red[wid + 8] = ss; }
    __syncthreads();
    s = 0.f; ss = 0.f;
    #pragma unroll
    for (int w = 0; w < 8; w++) { s += red[w]; ss += red[w + 8]; }
    const float mean = s * (1.f / D_);
    const float var = ss * (1.f / D_) - mean * mean;
    const float rstd = rsqrtf(var + 1e-5f);
    #pragma unroll
    for (int i = 0; i < 3; i++) {
        int c = threadIdx.x + i * 256;
        Y[(size_t)row * D_ + c] = (v[i] - mean) * rstd * g[c] + be[c];
    }
}

// ---------------------------------------------------------------------------
// Launch
// ---------------------------------------------------------------------------
extern "C" void kernel_launch(void* const* d_in, const int* in_sizes, int n_in,
                              void* d_out, int out_size)
{
    const float* x  = (const float*)d_in[0];
    const float* Wq = (const float*)d_in[1];
    const float* bq = (const float*)d_in[2];
    const float* Wk = (const float*)d_in[3];
    const float* bk = (const float*)d_in[4];
    const float* Wv = (const float*)d_in[5];
    const float* bv = (const float*)d_in[6];
    const float* Wo = (const float*)d_in[7];
    const float* bo = (const float*)d_in[8];
    const float* W1 = (const float*)d_in[9];
    const float* b1 = (const float*)d_in[10];
    const float* W2 = (const float*)d_in[11];
    const float* b2 = (const float*)d_in[12];
    const float* g1 = (const float*)d_in[13];
    const float* be1 = (const float*)d_in[14];
    const float* g2 = (const float*)d_in[15];
    const float* be2 = (const float*)d_in[16];
    float* out = (float*)d_out;

    float *Qp, *Kp, *Vp, *attnp, *t1p, *x1p, *ffp, *t2p;
    cudaGetSymbolAddress((void**)&Qp, g_Q);
    cudaGetSymbolAddress((void**)&Kp, g_K);
    cudaGetSymbolAddress((void**)&Vp, g_V);
    cudaGetSymbolAddress((void**)&attnp, g_attn);
    cudaGetSymbolAddress((void**)&t1p, g_t1);
    cudaGetSymbolAddress((void**)&x1p, g_x1);
    cudaGetSymbolAddress((void**)&ffp, g_ff);
    cudaGetSymbolAddress((void**)&t2p, g_t2);

    // QKV (fused over blockIdx.z)
    qkv_tc<<<dim3(D_ / 128, M_ / 128, 3), 256>>>(x, Wq, bq, Wk, bk, Wv, bv,
                                                 Qp, Kp, Vp);

    // Attention
    const int attn_smem = (3 * 64 * 68 + 64) * (int)sizeof(float);  // 52480
    cudaFuncSetAttribute(attn_tc, cudaFuncAttributeMaxDynamicSharedMemorySize,
                         attn_smem);
    attn_tc<<<dim3(S_ / 64, B_ * H_), 256, attn_smem>>>(Qp, Kp, Vp, attnp);

    // O-proj + residual, LN1
    gemm_tc<false, true><<<dim3(D_ / 128, M_ / 128), 256>>>(attnp, Wo, bo, x, t1p, D_, D_);
    ln_kernel<<<M_, 256>>>(t1p, g1, be1, x1p);

    // FFN
    gemm_tc<true, false><<<dim3(F_ / 128, M_ / 128), 256>>>(x1p, W1, b1, nullptr, ffp, F_, D_);
    gemm_tc<false, true><<<dim3(D_ / 128, M_ / 128), 256>>>(ffp, W2, b2, x1p, t2p, D_, F_);
    ln_kernel<<<M_, 256>>>(t2p, g2, be2, out);
}

// round 4
// speedup vs baseline: 2.1689x; 2.1689x over previous
#include <cuda_runtime.h>
#include <math_constants.h>
#include <mma.h>
#include <cuda_bf16.h>
#include <cstdint>

using namespace nvcuda;

// ---------------------------------------------------------------------------
// Problem constants
// ---------------------------------------------------------------------------
#define B_  2
#define S_  2048
#define D_  768
#define F_  3072
#define H_  12
#define HD_ 64
#define M_  (B_ * S_)   // 4096 rows

// ---------------------------------------------------------------------------
// Scratch
// ---------------------------------------------------------------------------
__device__ float g_Q[M_ * D_];
__device__ float g_K[M_ * D_];
__device__ float g_V[M_ * D_];
__device__ float g_attn[M_ * D_];
__device__ float g_t1[M_ * D_];
__device__ float g_x1[M_ * D_];
__device__ float g_ff[(size_t)M_ * F_];
__device__ float g_t2[M_ * D_];

// ---------------------------------------------------------------------------
// bf16 split helpers: x = hi + lo with hi = bf16(x), lo = bf16(x - hi).
// Products use hi*hi + hi*lo + lo*hi (lo*lo ~2^-18 dropped).
// ---------------------------------------------------------------------------
__device__ __forceinline__ void split_store4(float4 v,
                                             __nv_bfloat16* hp,
                                             __nv_bfloat16* lp)
{
    __nv_bfloat162 h0, h1, l0, l1;
    h0.x = __float2bfloat16_rn(v.x); h0.y = __float2bfloat16_rn(v.y);
    h1.x = __float2bfloat16_rn(v.z); h1.y = __float2bfloat16_rn(v.w);
    l0.x = __float2bfloat16_rn(v.x - __bfloat162float(h0.x));
    l0.y = __float2bfloat16_rn(v.y - __bfloat162float(h0.y));
    l1.x = __float2bfloat16_rn(v.z - __bfloat162float(h1.x));
    l1.y = __float2bfloat16_rn(v.w - __bfloat162float(h1.y));
    *(__nv_bfloat162*)(hp)     = h0;
    *(__nv_bfloat162*)(hp + 2) = h1;
    *(__nv_bfloat162*)(lp)     = l0;
    *(__nv_bfloat162*)(lp + 2) = l1;
}

using F16A  = wmma::fragment<wmma::matrix_a, 16, 16, 16, __nv_bfloat16, wmma::row_major>;
using F16Br = wmma::fragment<wmma::matrix_b, 16, 16, 16, __nv_bfloat16, wmma::row_major>;
using F16Bc = wmma::fragment<wmma::matrix_b, 16, 16, 16, __nv_bfloat16, wmma::col_major>;
using FragC = wmma::fragment<wmma::accumulator, 16, 16, 16, float>;

// ---------------------------------------------------------------------------
// bf16x3 GEMM: C[M,N] = A[M,K] @ W[K,N] + bias (+resid) (+ReLU)
// CTA tile 128x128, BK=32, 256 threads = 8 warps (2x4), warp tile 64x32.
// fp32 -> (hi,lo) bf16 split happens once per element at smem fill time;
// mainloop fragment loads are LDSM, mma is m16n16k16 bf16.
// ---------------------------------------------------------------------------
template <bool RELU, bool RES>
__device__ __forceinline__ void gemm_body(
    const float* __restrict__ A, const float* __restrict__ W,
    const float* __restrict__ bias, const float* __restrict__ resid,
    float* __restrict__ C, int N, int K, int bm, int bn)
{
    __shared__ __align__(16) __nv_bfloat16 Ah[128][40];
    __shared__ __align__(16) __nv_bfloat16 Al[128][40];
    __shared__ __align__(16) __nv_bfloat16 Bh[32][136];
    __shared__ __align__(16) __nv_bfloat16 Bl[32][136];
    __shared__ __align__(16) float bias_s[16][136];

    const int tid = threadIdx.x;
    const int wid = tid >> 5;
    const int wm = wid & 1;   // 0..1  (M)
    const int wn = wid >> 1;  // 0..3  (N)

    // replicate bias across 16 rows (for accumulator-layout fragment loads)
    #pragma unroll
    for (int p = 0; p < 8; p++) {
        int idx = tid + p * 256;
        bias_s[idx >> 7][idx & 127] = bias[bn + (idx & 127)];
    }

    FragC acc[4][2];
    #pragma unroll
    for (int i = 0; i < 4; i++)
        #pragma unroll
        for (int j = 0; j < 2; j++)
            wmma::fill_fragment(acc[i][j], 0.0f);

    const int arow = tid >> 3, acol = (tid & 7) << 2;
    const int brow = tid >> 5, bcol = (tid & 31) << 2;

    for (int kt = 0; kt < K; kt += 32) {
        #pragma unroll
        for (int p = 0; p < 4; p++) {
            int ar = arow + p * 32;
            float4 a4 = *(const float4*)&A[(size_t)(bm + ar) * K + kt + acol];
            split_store4(a4, &Ah[ar][acol], &Al[ar][acol]);
            int br = brow + p * 8;
            float4 w4 = *(const float4*)&W[(size_t)(kt + br) * N + bn + bcol];
            split_store4(w4, &Bh[br][bcol], &Bl[br][bcol]);
        }
        __syncthreads();

        #pragma unroll
        for (int kk = 0; kk < 32; kk += 16) {
            F16A ah[4], al[4];
            #pragma unroll
            for (int i = 0; i < 4; i++) {
                wmma::load_matrix_sync(ah[i], &Ah[wm * 64 + i * 16][kk], 40);
                wmma::load_matrix_sync(al[i], &Al[wm * 64 + i * 16][kk], 40);
            }
            #pragma unroll
            for (int j = 0; j < 2; j++) {
                F16Br bh, bl;
                wmma::load_matrix_sync(bh, &Bh[kk][wn * 32 + j * 16], 136);
                wmma::load_matrix_sync(bl, &Bl[kk][wn * 32 + j * 16], 136);
                #pragma unroll
                for (int i = 0; i < 4; i++) {
                    wmma::mma_sync(acc[i][j], ah[i], bh, acc[i][j]);
                    wmma::mma_sync(acc[i][j], ah[i], bl, acc[i][j]);
                    wmma::mma_sync(acc[i][j], al[i], bh, acc[i][j]);
                }
            }
        }
        __syncthreads();
    }

    // epilogue: bias (+resid) (+relu), store straight to global
    #pragma unroll
    for (int i = 0; i < 4; i++) {
        int r0 = bm + wm * 64 + i * 16;
        #pragma unroll
        for (int j = 0; j < 2; j++) {
            int c0 = bn + wn * 32 + j * 16;
            FragC bf;
            wmma::load_matrix_sync(bf, &bias_s[0][wn * 32 + j * 16], 136, wmma::mem_row_major);
            #pragma unroll
            for (int t = 0; t < acc[i][j].num_elements; t++)
                acc[i][j].x[t] += bf.x[t];
            if (RES) {
                FragC rf;
                wmma::load_matrix_sync(rf, resid + (size_t)r0 * N + c0, N, wmma::mem_row_major);
                #pragma unroll
                for (int t = 0; t < acc[i][j].num_elements; t++)
                    acc[i][j].x[t] += rf.x[t];
            }
            if (RELU) {
                #pragma unroll
                for (int t = 0; t < acc[i][j].num_elements; t++)
                    acc[i][j].x[t] = fmaxf(acc[i][j].x[t], 0.0f);
            }
            wmma::store_matrix_sync(C + (size_t)r0 * N + c0, acc[i][j], N, wmma::mem_row_major);
        }
    }
}

template <bool RELU, bool RES>
__global__ __launch_bounds__(256)
void gemm_tc(const float* __restrict__ A, const float* __restrict__ W,
             const float* __restrict__ bias, const float* __restrict__ resid,
             float* __restrict__ C, int N, int K)
{
    gemm_body<RELU, RES>(A, W, bias, resid, C, N, K,
                         blockIdx.y * 128, blockIdx.x * 128);
}

// Fused QKV: blockIdx.z selects projection
__global__ __launch_bounds__(256)
void qkv_tc(const float* __restrict__ x,
            const float* __restrict__ Wq, const float* __restrict__ bq,
            const float* __restrict__ Wk, const float* __restrict__ bk,
            const float* __restrict__ Wv, const float* __restrict__ bv,
            float* __restrict__ Q, float* __restrict__ K, float* __restrict__ V)
{
    const float* W = blockIdx.z == 0 ? Wq : (blockIdx.z == 1 ? Wk : Wv);
    const float* bb = blockIdx.z == 0 ? bq : (blockIdx.z == 1 ? bk : bv);
    float* C = blockIdx.z == 0 ? Q : (blockIdx.z == 1 ? K : V);
    gemm_body<false, false>(x, W, bb, nullptr, C, D_, D_,
                            blockIdx.y * 128, blockIdx.x * 128);
}

// ---------------------------------------------------------------------------
// Attention with bf16x3 wmma. 64 q-rows per CTA, key blocks of 64.
// No running max (scores bounded; clamp at 80 guards inf). O accumulates in
// fragments with no rescale; one 1/l normalize at the end.
// smem regions (dynamic):
//   Qh/Ql [64][72] bf16, Kh/Kl [64][72] bf16 (K tile then V tile),
//   Ph/Pl [64][72] bf16, Ss [64][68] f32, lrow[64] f32.
// ---------------------------------------------------------------------------
#define AT_LD 72
__global__ __launch_bounds__(256)
void attn_tc(const float* __restrict__ Q, const float* __restrict__ K,
             const float* __restrict__ V, float* __restrict__ O)
{
    extern __shared__ __align__(16) char smraw[];
    __nv_bfloat16* Qh = (__nv_bfloat16*)smraw;                    // 9216 B
    __nv_bfloat16* Ql = Qh + 64 * AT_LD;
    __nv_bfloat16* Kh = Ql + 64 * AT_LD;
    __nv_bfloat16* Kl = Kh + 64 * AT_LD;
    __nv_bfloat16* Ph = Kl + 64 * AT_LD;
    __nv_bfloat16* Pl = Ph + 64 * AT_LD;
    float* Ss   = (float*)(Pl + 64 * AT_LD);                      // [64][68]
    float* lrow = Ss + 64 * 68;

    const int tid = threadIdx.x;
    const int wid = tid >> 5;
    const int wm = wid & 1;    // 0..1 -> 32-row half
    const int wn = wid >> 1;   // 0..3 -> 16-col slice
    const int bh = blockIdx.y;
    const int b = bh / H_;
    const int h = bh % H_;
    const int q0 = blockIdx.x * 64;
    const size_t hb = (size_t)b * S_ * D_ + (size_t)h * HD_;

    const int lr = tid >> 2;          // 0..63 row
    const int lc = (tid & 3) << 4;    // 0,16,32,48

    // Q tile (scale 1/sqrt(64) folded in), split into hi/lo bf16
    {
        const float* src = Q + hb + (size_t)(q0 + lr) * D_ + lc;
        #pragma unroll
        for (int i = 0; i < 4; i++) {
            float4 v = *(const float4*)(src + i * 4);
            v.x *= 0.125f; v.y *= 0.125f; v.z *= 0.125f; v.w *= 0.125f;
            split_store4(v, &Qh[lr * AT_LD + lc + i * 4], &Ql[lr * AT_LD + lc + i * 4]);
        }
    }
    if (tid < 64) lrow[tid] = 0.0f;

    FragC oacc[2];
    wmma::fill_fragment(oacc[0], 0.0f);
    wmma::fill_fragment(oacc[1], 0.0f);

    for (int kt = 0; kt < S_; kt += 64) {
        // K tile [key][d], split
        {
            const float* src = K + hb + (size_t)(kt + lr) * D_ + lc;
            #pragma unroll
            for (int i = 0; i < 4; i++) {
                float4 v = *(const float4*)(src + i * 4);
                split_store4(v, &Kh[lr * AT_LD + lc + i * 4], &Kl[lr * AT_LD + lc + i * 4]);
            }
        }
        __syncthreads();

        // S = Q @ K^T  (bf16x3)
        FragC sacc[2];
        wmma::fill_fragment(sacc[0], 0.0f);
        wmma::fill_fragment(sacc[1], 0.0f);
        #pragma unroll
        for (int dd = 0; dd < 64; dd += 16) {
            F16A qh[2], ql[2];
            #pragma unroll
            for (int i = 0; i < 2; i++) {
                wmma::load_matrix_sync(qh[i], &Qh[(wm * 32 + i * 16) * AT_LD + dd], AT_LD);
                wmma::load_matrix_sync(ql[i], &Ql[(wm * 32 + i * 16) * AT_LD + dd], AT_LD);
            }
            F16Bc kh, kl;
            wmma::load_matrix_sync(kh, &Kh[(wn * 16) * AT_LD + dd], AT_LD);
            wmma::load_matrix_sync(kl, &Kl[(wn * 16) * AT_LD + dd], AT_LD);
            #pragma unroll
            for (int i = 0; i < 2; i++) {
                wmma::mma_sync(sacc[i], qh[i], kh, sacc[i]);
                wmma::mma_sync(sacc[i], qh[i], kl, sacc[i]);
                wmma::mma_sync(sacc[i], ql[i], kh, sacc[i]);
            }
        }
        #pragma unroll
        for (int i = 0; i < 2; i++)
            wmma::store_matrix_sync(&Ss[(wm * 32 + i * 16) * 68 + wn * 16],
                                    sacc[i], 68, wmma::mem_row_major);
        __syncthreads();

        // exp (no max-shift) + row-sum; write P as bf16 hi/lo; stage V into Kh/Kl
        {
            int row = tid >> 2;
            float* p = &Ss[row * 68 + lc];
            float s = 0.0f;
            #pragma unroll
            for (int i = 0; i < 16; i += 2) {
                float e0 = __expf(fminf(p[i], 80.0f));
                float e1 = __expf(fminf(p[i + 1], 80.0f));
                s += e0 + e1;
                __nv_bfloat162 hh, ll;
                hh.x = __float2bfloat16_rn(e0);
                hh.y = __float2bfloat16_rn(e1);
                ll.x = __float2bfloat16_rn(e0 - __bfloat162float(hh.x));
                ll.y = __float2bfloat16_rn(e1 - __bfloat162float(hh.y));
                *(__nv_bfloat162*)&Ph[row * AT_LD + lc + i] = hh;
                *(__nv_bfloat162*)&Pl[row * AT_LD + lc + i] = ll;
            }
            s += __shfl_xor_sync(0xffffffffu, s, 1);
            s += __shfl_xor_sync(0xffffffffu, s, 2);
            if ((tid & 3) == 0) lrow[row] += s;

            const float* src = V + hb + (size_t)(kt + lr) * D_ + lc;
            #pragma unroll
            for (int i = 0; i < 4; i++) {
                float4 v = *(const float4*)(src + i * 4);
                split_store4(v, &Kh[lr * AT_LD + lc + i * 4], &Kl[lr * AT_LD + lc + i * 4]);
            }
        }
        __syncthreads();

        // O += P @ V  (bf16x3)
        #pragma unroll
        for (int kk = 0; kk < 64; kk += 16) {
            F16A ph[2], pl[2];
            #pragma unroll
            for (int i = 0; i < 2; i++) {
                wmma::load_matrix_sync(ph[i], &Ph[(wm * 32 + i * 16) * AT_LD + kk], AT_LD);
                wmma::load_matrix_sync(pl[i], &Pl[(wm * 32 + i * 16) * AT_LD + kk], AT_LD);
            }
            F16Br vh, vl;
            wmma::load_matrix_sync(vh, &Kh[kk * AT_LD + wn * 16], AT_LD);
            wmma::load_matrix_sync(vl, &Kl[kk * AT_LD + wn * 16], AT_LD);
            #pragma unroll
            for (int i = 0; i < 2; i++) {
                wmma::mma_sync(oacc[i], ph[i], vh, oacc[i]);
                wmma::mma_sync(oacc[i], ph[i], vl, oacc[i]);
                wmma::mma_sync(oacc[i], pl[i], vh, oacc[i]);
            }
        }
        __syncthreads();  // before next block overwrites Kh/Kl/Ss
    }

    // normalize by 1/l and write out
    #pragma unroll
    for (int i = 0; i < 2; i++)
        wmma::store_matrix_sync(&Ss[(wm * 32 + i * 16) * 68 + wn * 16],
                                oacc[i], 68, wmma::mem_row_major);
    __syncthreads();
    {
        int row = tid >> 2;
        float inv = 1.0f / lrow[row];
        float* p = &Ss[row * 68 + lc];
        float* dst = O + (size_t)((size_t)b * S_ + q0 + row) * D_ + h * HD_ + lc;
        #pragma unroll
        for (int i = 0; i < 4; i++) {
            float4 v = *(float4*)&p[i * 4];
            v.x *= inv; v.y *= inv; v.z *= inv; v.w *= inv;
            *(float4*)(dst + i * 4) = v;
        }
    }
}

// ---------------------------------------------------------------------------
// Row LayerNorm over D_=768 columns. One CTA per row.
// ---------------------------------------------------------------------------
__global__ __launch_bounds__(256)
void ln_kernel(const float* __restrict__ X, const float* __restrict__ g,
               const float* __restrict__ be, float* __restrict__ Y)
{
    const int row = blockIdx.x;
    const float* xr = X + (size_t)row * D_;
    float v[3];
    float s = 0.f, ss = 0.f;
    #pragma unroll
    for (int i = 0; i < 3; i++) {
        v[i] = xr[threadIdx.x + i * 256];
        s += v[i];
        ss += v[i] * v[i];
    }
    #pragma unroll
    for (int o = 16; o; o >>= 1) {
        s += __shfl_xor_sync(0xffffffffu, s, o);
        ss += __shfl_xor_sync(0xffffffffu, ss, o);
    }
    __shared__ float red[16];
    const int wid = threadIdx.x >> 5, lid = threadIdx.x & 31;
    if (lid == 0) { red[wid] = s; red[wid + 8] = ss; }
    __syncthreads();
    s = 0.f; ss = 0.f;
    #pragma unroll
    for (int w = 0; w < 8; w++) { s += red[w]; ss += red[w + 8]; }
    const float mean = s * (1.f / D_);
    const float var = ss * (1.f / D_) - mean * mean;
    const float rstd = rsqrtf(var + 1e-5f);
    #pragma unroll
    for (int i = 0; i < 3; i++) {
        int c = threadIdx.x + i * 256;
        Y[(size_t)row * D_ + c] = (v[i] - mean) * rstd * g[c] + be[c];
    }
}

// ---------------------------------------------------------------------------
// Launch
// ---------------------------------------------------------------------------
extern "C" void kernel_launch(void* const* d_in, const int* in_sizes, int n_in,
                              void* d_out, int out_size)
{
    const float* x  = (const float*)d_in[0];
    const float* Wq = (const float*)d_in[1];
    const float* bq = (const float*)d_in[2];
    const float* Wk = (const float*)d_in[3];
    const float* bk = (const float*)d_in[4];
    const float* Wv = (const float*)d_in[5];
    const float* bv = (const float*)d_in[6];
    const float* Wo = (const float*)d_in[7];
    const float* bo = (const float*)d_in[8];
    const float* W1 = (const float*)d_in[9];
    const float* b1 = (const float*)d_in[10];
    const float* W2 = (const float*)d_in[11];
    const float* b2 = (const float*)d_in[12];
    const float* g1 = (const float*)d_in[13];
    const float* be1 = (const float*)d_in[14];
    const float* g2 = (const float*)d_in[15];
    const float* be2 = (const float*)d_in[16];
    float* out = (float*)d_out;

    float *Qp, *Kp, *Vp, *attnp, *t1p, *x1p, *ffp, *t2p;
    cudaGetSymbolAddress((void**)&Qp, g_Q);
    cudaGetSymbolAddress((void**)&Kp, g_K);
    cudaGetSymbolAddress((void**)&Vp, g_V);
    cudaGetSymbolAddress((void**)&attnp, g_attn);
    cudaGetSymbolAddress((void**)&t1p, g_t1);
    cudaGetSymbolAddress((void**)&x1p, g_x1);
    cudaGetSymbolAddress((void**)&ffp, g_ff);
    cudaGetSymbolAddress((void**)&t2p, g_t2);

    // QKV (fused over blockIdx.z)
    qkv_tc<<<dim3(D_ / 128, M_ / 128, 3), 256>>>(x, Wq, bq, Wk, bk, Wv, bv,
                                                 Qp, Kp, Vp);

    // Attention
    const int attn_smem = 6 * 64 * AT_LD * 2 + (64 * 68 + 64) * 4;  // 72960 B
    cudaFuncSetAttribute(attn_tc, cudaFuncAttributeMaxDynamicSharedMemorySize,
                         attn_smem);
    attn_tc<<<dim3(S_ / 64, B_ * H_), 256, attn_smem>>>(Qp, Kp, Vp, attnp);

    // O-proj + residual, LN1
    gemm_tc<false, true><<<dim3(D_ / 128, M_ / 128), 256>>>(attnp, Wo, bo, x, t1p, D_, D_);
    ln_kernel<<<M_, 256>>>(t1p, g1, be1, x1p);

    // FFN
    gemm_tc<true, false><<<dim3(F_ / 128, M_ / 128), 256>>>(x1p, W1, b1, nullptr, ffp, F_, D_);
    gemm_tc<false, true><<<dim3(D_ / 128, M_ / 128), 256>>>(ffp, W2, b2, x1p, t2p, D_, F_);
    ln_kernel<<<M_, 256>>>(t2p, g2, be2, out);
}